// round 10
// baseline (speedup 1.0000x reference)
#include <cuda_runtime.h>
#include <cstdint>

#define N_ 50000
#define K_ 32
#define D_ 128
#define EPS_ 1e-12f
#define WARPS_PER_BLOCK 8
#define THREADS_ (WARPS_PER_BLOCK * 32)
#define NBLOCKS_ ((N_ + WARPS_PER_BLOCK - 1) / WARPS_PER_BLOCK)   // 6250

__device__ uint16_t g_hi[(size_t)N_ * D_];   // fp32 bits [31:16]  (12.8 MB)
__device__ uint8_t  g_lo[(size_t)N_ * D_];   // fp32 bits [15:8]   (6.4 MB)
__device__ float    g_bnorm[N_];             // ||y_j||^2, exact fp32 (200 KB)
__device__ double   g_block_partials[NBLOCKS_];
__device__ unsigned g_ticket = 0;            // returns to 0 each run (graph-replay safe)

// Warp-per-row prep: quantize row to 24-bit planes AND compute its exact norm.
__global__ __launch_bounds__(THREADS_)
void snl_prep_kernel(const float* __restrict__ emb) {
    const int warp = threadIdx.x >> 5;
    const int lane = threadIdx.x & 31;
    const int i = blockIdx.x * WARPS_PER_BLOCK + warp;

    const float4 y = reinterpret_cast<const float4*>(emb + (size_t)i * D_)[lane];

    // norm partial + butterfly
    float nrm = y.x * y.x;
    nrm = fmaf(y.y, y.y, nrm);
    nrm = fmaf(y.z, y.z, nrm);
    nrm = fmaf(y.w, y.w, nrm);
    #pragma unroll
    for (int o = 16; o; o >>= 1) nrm += __shfl_xor_sync(0xffffffffu, nrm, o);
    if (lane == 0) g_bnorm[i] = nrm;

    // round fp32 to 24 bits (int add of 0x80 on raw bits; carry handled by IEEE layout)
    const unsigned r0 = __float_as_uint(y.x) + 0x80u;
    const unsigned r1 = __float_as_uint(y.y) + 0x80u;
    const unsigned r2 = __float_as_uint(y.z) + 0x80u;
    const unsigned r3 = __float_as_uint(y.w) + 0x80u;

    ushort4 h;
    h.x = (unsigned short)(r0 >> 16); h.y = (unsigned short)(r1 >> 16);
    h.z = (unsigned short)(r2 >> 16); h.w = (unsigned short)(r3 >> 16);
    uchar4 l;
    l.x = (unsigned char)(r0 >> 8); l.y = (unsigned char)(r1 >> 8);
    l.z = (unsigned char)(r2 >> 8); l.w = (unsigned char)(r3 >> 8);

    reinterpret_cast<ushort4*>(g_hi + (size_t)i * D_)[lane] = h;
    reinterpret_cast<uchar4*>(g_lo + (size_t)i * D_)[lane] = l;
}

__global__ __launch_bounds__(THREADS_, 6)
void snl_main_kernel(const float* __restrict__ emb,
                     const float* __restrict__ p,
                     const int* __restrict__ anchor,
                     float* __restrict__ out /* [0]=loss, [1..]=q */) {
    __shared__ double loss_s[WARPS_PER_BLOCK];
    __shared__ double red_s[THREADS_];
    __shared__ bool   is_last;

    const int warp = threadIdx.x >> 5;
    const int lane = threadIdx.x & 31;
    const int i = blockIdx.x * WARPS_PER_BLOCK + warp;   // 6250*8 == 50000 exactly
    float* __restrict__ out_q = out + 1;

    // yi exact, pre-scaled by 2 so the dot partial directly accumulates 2*a.b
    const float4 a0 = reinterpret_cast<const float4*>(emb + (size_t)i * D_)[lane];
    const float4 a = make_float4(2.0f * a0.x, 2.0f * a0.y, 2.0f * a0.z, 2.0f * a0.w);

    int j_mine = anchor[(size_t)i * K_ + lane];
    j_mine = max(0, min(j_mine, N_ - 1));                // defensive clamp

    const bool hi16 = (lane & 16) != 0;
    const bool hi8  = (lane & 8) != 0;

    // per-anchor dot partial: lane t covers dims 4t..4t+3 (PRMT decode, no I2F)
    auto partial = [&](int jr) -> float {
        const uint2    hw = *reinterpret_cast<const uint2*>(g_hi + (size_t)jr * D_ + 4 * lane);
        const unsigned lw = *reinterpret_cast<const unsigned*>(g_lo + (size_t)jr * D_ + 4 * lane);
        const float bx = __uint_as_float(__byte_perm(hw.x, lw, 0x1044));
        const float by = __uint_as_float(__byte_perm(hw.x, lw, 0x3255));
        const float bz = __uint_as_float(__byte_perm(hw.y, lw, 0x1066));
        const float bw = __uint_as_float(__byte_perm(hw.y, lw, 0x3277));
        float pr = a.x * bx;
        pr = fmaf(a.y, by, pr);
        pr = fmaf(a.z, bz, pr);
        pr = fmaf(a.w, bw, pr);
        return pr;
    };

    // 4-way folded partials: w[g] covers anchors 4g..4g+3 (8 live registers).
    float w[K_ / 4];
    #pragma unroll
    for (int g = 0; g < K_ / 4; g++) {
        const int jr0 = __shfl_sync(0xffffffffu, j_mine, 4 * g);
        const int jr1 = __shfl_sync(0xffffffffu, j_mine, 4 * g + 1);
        const int jr2 = __shfl_sync(0xffffffffu, j_mine, 4 * g + 2);
        const int jr3 = __shfl_sync(0xffffffffu, j_mine, 4 * g + 3);
        const float p0 = partial(jr0);
        const float p1 = partial(jr1);
        const float p2 = partial(jr2);
        const float p3 = partial(jr3);

        float s01 = hi16 ? p0 : p1;
        float u01 = (hi16 ? p1 : p0) + __shfl_xor_sync(0xffffffffu, s01, 16);
        float s23 = hi16 ? p2 : p3;
        float u23 = (hi16 ? p3 : p2) + __shfl_xor_sync(0xffffffffu, s23, 16);
        float s8 = hi8 ? u01 : u23;
        w[g] = (hi8 ? u23 : u01) + __shfl_xor_sync(0xffffffffu, s8, 8);
    }

    // Recursive halving on 8 values: 7 shuffles; lane l ends with anchor a(l).
    #pragma unroll
    for (int s = 4; s >= 1; s >>= 1) {
        const bool upper = (lane & s) != 0;
        #pragma unroll
        for (int k = 0; k < s; k++) {
            const float send = upper ? w[k] : w[k + s];
            const float recv = __shfl_xor_sync(0xffffffffu, send, s);
            w[k] = (upper ? w[k + s] : w[k]) + recv;
        }
    }
    const int acol = 4 * (lane & 7) + 2 * ((lane >> 3) & 1) + ((lane >> 4) & 1);
    const int jcol = __shfl_sync(0xffffffffu, j_mine, acol);

    // shifted logit: s = 2*a.b - ||b||^2  (||a||^2 constant cancels in log-softmax)
    const float sc = w[0] - g_bnorm[jcol];

    // softmax over the 32 lanes
    float m = sc;
    #pragma unroll
    for (int o = 16; o; o >>= 1) m = fmaxf(m, __shfl_xor_sync(0xffffffffu, m, o));
    const float e = __expf(sc - m);
    float sum = e;
    #pragma unroll
    for (int o = 16; o; o >>= 1) sum += __shfl_xor_sync(0xffffffffu, sum, o);
    const float lse = m + __logf(sum);
    const float logq = sc - lse;
    const float q = __expf(logq);

    const float pv = p[(size_t)i * K_ + acol];
    out_q[(size_t)i * K_ + acol] = q;

    float contrib = pv * (__logf(pv + EPS_) - logq);
    #pragma unroll
    for (int o = 16; o; o >>= 1) contrib += __shfl_xor_sync(0xffffffffu, contrib, o);
    if (lane == 0) loss_s[warp] = (double)contrib;
    __syncthreads();

    if (threadIdx.x == 0) {
        double blk = 0.0;
        #pragma unroll
        for (int w2 = 0; w2 < WARPS_PER_BLOCK; w2++) blk += loss_s[w2];
        g_block_partials[blockIdx.x] = blk;
        __threadfence();
        unsigned t = atomicAdd(&g_ticket, 1u);
        is_last = (t == (unsigned)(NBLOCKS_ - 1));
    }
    __syncthreads();

    if (is_last) {
        __threadfence();
        double acc = 0.0;
        for (int b = threadIdx.x; b < NBLOCKS_; b += THREADS_)
            acc += g_block_partials[b];
        red_s[threadIdx.x] = acc;
        __syncthreads();
        #pragma unroll
        for (int o = THREADS_ / 2; o; o >>= 1) {
            if (threadIdx.x < o) red_s[threadIdx.x] += red_s[threadIdx.x + o];
            __syncthreads();
        }
        if (threadIdx.x == 0) {
            out[0] = (float)(red_s[0] / (double)N_);
            g_ticket = 0;
        }
    }
}

extern "C" void kernel_launch(void* const* d_in, const int* in_sizes, int n_in,
                              void* d_out, int out_size) {
    const float* emb    = (const float*)d_in[0];  // output_embedding [N, D] f32
    const float* p      = (const float*)d_in[1];  // input_similarity [N, K] f32
    const int*   anchor = (const int*)d_in[2];    // anchor_idx [N, K] int32
    float* out = (float*)d_out;                   // [0]=loss, [1..]=q row-major

    snl_prep_kernel<<<NBLOCKS_, THREADS_>>>(emb);
    snl_main_kernel<<<NBLOCKS_, THREADS_>>>(emb, p, anchor, out);
}